// round 11
// baseline (speedup 1.0000x reference)
#include <cuda_runtime.h>
#include <cuda_bf16.h>
#include <cuda_fp16.h>
#include <cstdint>
#include <cstring>

#define NN 100000
#define DD 128
#define EMAX 1600000
#define NP 100096          // 782 * 128 (padded rows)
#define NBLK 782
#define TSTRIDE 136        // padded bf16 row stride: conflict-free ldmatrix
#define TILE (128 * TSTRIDE)

// ---------------- scratch (device globals: no allocation allowed) ----------------
__device__ float g_K[NP * DD];
__device__ __half g_QVh[NP * 256];         // per node: q fp16[0..128), v fp16[128..256)
__device__ float g_S[NP * DD];
__device__ __nv_bfloat16 g_Ahi[NP * DD];   // layer-2 GEMM input (pad rows stay 0)
__device__ __nv_bfloat16 g_Alo[NP * DD];
__device__ __nv_bfloat16 g_Whi[512 * 128]; // [n_out][k], n_out = concat(k,q,v,s)
__device__ __nv_bfloat16 g_Wlo[512 * 128];
__device__ float4 g_P3[NP];
__device__ int g_counts[NN];
__device__ int g_rowoff[NN + 1];
__device__ int g_cursor[NN];
__device__ int g_srcsorted[EMAX];

// ---------------- helpers ----------------
__device__ __forceinline__ uint32_t smem_u32(const void* p) {
    uint32_t a;
    asm("{ .reg .u64 t; cvta.to.shared.u64 t, %1; cvt.u32.u64 %0, t; }" : "=r"(a) : "l"(p));
    return a;
}

#define LDSM_X4(r0, r1, r2, r3, addr)                                          \
    asm volatile("ldmatrix.sync.aligned.m8n8.x4.shared.b16 {%0,%1,%2,%3}, [%4];" \
                 : "=r"(r0), "=r"(r1), "=r"(r2), "=r"(r3) : "r"(addr))

#define MMA16816(d, a, b0, b1)                                                 \
    asm volatile("mma.sync.aligned.m16n8k16.row.col.f32.bf16.bf16.f32 "        \
                 "{%0,%1,%2,%3}, {%4,%5,%6,%7}, {%8,%9}, {%0,%1,%2,%3};"       \
                 : "+f"((d)[0]), "+f"((d)[1]), "+f"((d)[2]), "+f"((d)[3])      \
                 : "r"((a)[0]), "r"((a)[1]), "r"((a)[2]), "r"((a)[3]),         \
                   "r"(b0), "r"(b1))

// ---------------- MUFU-based sigmoid ----------------
__device__ __forceinline__ float fsig(float t) {
    return __fdividef(1.0f, 1.0f + __expf(-t));
}

// fp16 pair (as uint32) -> float2
__device__ __forceinline__ float2 h2f(uint32_t u) {
    __half2 h;
    memcpy(&h, &u, 4);
    return __half22float2(h);
}

// safe bf16 hi/lo split pack: two floats -> (hi_pair, lo_pair) uint32s
__device__ __forceinline__ void pack_hl(float a, float b, uint32_t& hp, uint32_t& lp) {
    __nv_bfloat16 ha = __float2bfloat16(a);
    __nv_bfloat16 hb = __float2bfloat16(b);
    __nv_bfloat16 la = __float2bfloat16(a - __bfloat162float(ha));
    __nv_bfloat16 lb = __float2bfloat16(b - __bfloat162float(hb));
    hp = (uint32_t)__bfloat16_as_ushort(ha) | ((uint32_t)__bfloat16_as_ushort(hb) << 16);
    lp = (uint32_t)__bfloat16_as_ushort(la) | ((uint32_t)__bfloat16_as_ushort(lb) << 16);
}

// ---------------- CSR build ----------------
__global__ void zero_counts_k(int n) {
    int i = blockIdx.x * blockDim.x + threadIdx.x;
    if (i < n) g_counts[i] = 0;
}
__global__ void hist_k(const int* __restrict__ dst, int e) {
    int i = blockIdx.x * blockDim.x + threadIdx.x;
    if (i < e) atomicAdd(&g_counts[dst[i]], 1);
}
__global__ void scan_k(int n) {
    __shared__ int sums[1024];
    int tid = threadIdx.x;
    int chunk = (n + 1023) >> 10;
    int b = tid * chunk, e = min(b + chunk, n);
    int s = 0;
    for (int i = b; i < e; i++) s += g_counts[i];
    sums[tid] = s;
    __syncthreads();
    for (int off = 1; off < 1024; off <<= 1) {
        int v = (tid >= off) ? sums[tid - off] : 0;
        __syncthreads();
        sums[tid] += v;
        __syncthreads();
    }
    int run = tid ? sums[tid - 1] : 0;
    for (int i = b; i < e; i++) {
        g_rowoff[i] = run;
        g_cursor[i] = run;
        run += g_counts[i];
    }
    if (tid == 1023) g_rowoff[n] = sums[1023];
}
__global__ void scatter_k(const int* __restrict__ src, const int* __restrict__ dst, int e) {
    int i = blockIdx.x * blockDim.x + threadIdx.x;
    if (i < e) {
        int p = atomicAdd(&g_cursor[dst[i]], 1);
        g_srcsorted[p] = src[i];
    }
}

// ---------------- weight packing ----------------
__global__ void packw_k(const float* __restrict__ Wk, const float* __restrict__ Wq,
                        const float* __restrict__ Wv, const float* __restrict__ Ws) {
    int i = blockIdx.x * blockDim.x + threadIdx.x;   // 512*128
    if (i >= 512 * 128) return;
    int n = i >> 7, k = i & 127;
    const float* W = (n < 128) ? Wk : (n < 256) ? Wq : (n < 384) ? Wv : Ws;
    float v = W[k * 128 + (n & 127)];
    __nv_bfloat16 h = __float2bfloat16(v);
    g_Whi[i] = h;
    g_Wlo[i] = __float2bfloat16(v - __bfloat162float(h));
}

// ---------------- mma.sync bf16 split GEMM, A-resident column loop ----------------
// CTA: 128 rows x ALL 512 cols; A (hi+lo) loaded once, 4 col-blocks with
// double-buffered B tiles. K/S epilogue fp32; Q/V epilogue fp16 (halves agg traffic).
// acc = Ahi*Bhi + Alo*Bhi + Ahi*Blo  (fp32 accum; rel err ~2^-17)
__device__ __forceinline__ void load_B(__nv_bfloat16* Bh, __nv_bfloat16* Bl, int by, int tid) {
    const __nv_bfloat16* GBH = g_Whi + (size_t)by * 128 * 128;
    const __nv_bfloat16* GBL = g_Wlo + (size_t)by * 128 * 128;
#pragma unroll
    for (int i = 0; i < 8; i++) {
        int c = tid + i * 256;
        int r = c >> 4, col = (c & 15) * 8;
        *(uint4*)(Bh + r * TSTRIDE + col) = *(const uint4*)(GBH + r * 128 + col);
        *(uint4*)(Bl + r * TSTRIDE + col) = *(const uint4*)(GBL + r * 128 + col);
    }
}

template <int SRC>
__global__ void __launch_bounds__(256, 1) mma_gemm(
    const float* __restrict__ bias, const float* __restrict__ xin, int nrows)
{
    extern __shared__ __nv_bfloat16 sm[];
    __nv_bfloat16* Ah = sm;
    __nv_bfloat16* Al = sm + TILE;
    __nv_bfloat16* Bbuf[2][2] = {{sm + 2 * TILE, sm + 3 * TILE},
                                 {sm + 4 * TILE, sm + 5 * TILE}};

    int tid = threadIdx.x;
    int row0 = blockIdx.x * 128;

    // ---- load A once ----
    if (SRC == 0) {
#pragma unroll
        for (int i = 0; i < 8; i++) {
            int c = tid + i * 256;
            int r = c >> 4, col = (c & 15) * 8;
            *(uint4*)(Ah + r * TSTRIDE + col) = *(const uint4*)(g_Ahi + (size_t)(row0 + r) * 128 + col);
            *(uint4*)(Al + r * TSTRIDE + col) = *(const uint4*)(g_Alo + (size_t)(row0 + r) * 128 + col);
        }
    } else {
#pragma unroll
        for (int i = 0; i < 16; i++) {
            int c = tid + i * 256;
            int r = c >> 5, col = (c & 31) * 4;
            float4 v = make_float4(0.f, 0.f, 0.f, 0.f);
            if (row0 + r < nrows)
                v = *(const float4*)(xin + (size_t)(row0 + r) * 128 + col);
            uint32_t h0, l0, h1, l1;
            pack_hl(v.x, v.y, h0, l0);
            pack_hl(v.z, v.w, h1, l1);
            *(uint2*)(Ah + r * TSTRIDE + col) = make_uint2(h0, h1);
            *(uint2*)(Al + r * TSTRIDE + col) = make_uint2(l0, l1);
        }
    }
    // ---- B for col-block 0 ----
    load_B(Bbuf[0][0], Bbuf[0][1], 0, tid);
    __syncthreads();

    int w = tid >> 5, lane = tid & 31;
    int m_base = (w & 3) * 32;
    int n_base = (w >> 2) * 64;

    // ldmatrix address patterns
    int a_row = lane & 15, a_colsel = (lane >> 4) * 8;          // A x4: m16 x k16
    int b_grp = lane >> 3;                                      // B x4: n16 x k16
    int b_row = (b_grp >> 1) * 8 + (lane & 7);
    int b_col = (b_grp & 1) * 8;

    uint32_t sAh = smem_u32(Ah), sAl = smem_u32(Al);
    int r_in = lane >> 2;
    int c_in = (lane & 3) * 2;

    for (int by = 0; by < 4; by++) {
        int buf = by & 1;
        // prefetch next col-block's B into the other buffer (hidden under MMAs)
        if (by < 3) load_B(Bbuf[buf ^ 1][0], Bbuf[buf ^ 1][1], by + 1, tid);

        uint32_t sBh = smem_u32(Bbuf[buf][0]), sBl = smem_u32(Bbuf[buf][1]);

        float acc[2][8][4];
#pragma unroll
        for (int mi = 0; mi < 2; mi++)
#pragma unroll
            for (int ni = 0; ni < 8; ni++)
#pragma unroll
                for (int j = 0; j < 4; j++) acc[mi][ni][j] = 0.0f;

#pragma unroll
        for (int ks = 0; ks < 8; ks++) {
            int k0 = ks * 16;
            uint32_t ah[2][4], al[2][4], bh[4][4], bl[4][4];
#pragma unroll
            for (int mi = 0; mi < 2; mi++) {
                uint32_t off = (uint32_t)((m_base + mi * 16 + a_row) * TSTRIDE + k0 + a_colsel) * 2;
                LDSM_X4(ah[mi][0], ah[mi][1], ah[mi][2], ah[mi][3], sAh + off);
                LDSM_X4(al[mi][0], al[mi][1], al[mi][2], al[mi][3], sAl + off);
            }
#pragma unroll
            for (int j = 0; j < 4; j++) {
                uint32_t off = (uint32_t)((n_base + j * 16 + b_row) * TSTRIDE + k0 + b_col) * 2;
                LDSM_X4(bh[j][0], bh[j][1], bh[j][2], bh[j][3], sBh + off);
                LDSM_X4(bl[j][0], bl[j][1], bl[j][2], bl[j][3], sBl + off);
            }
#pragma unroll
            for (int mi = 0; mi < 2; mi++)
#pragma unroll
                for (int ni = 0; ni < 8; ni++) {
                    int j = ni >> 1, h = (ni & 1) * 2;
                    MMA16816(acc[mi][ni], ah[mi], bh[j][h], bh[j][h + 1]);
                    MMA16816(acc[mi][ni], al[mi], bh[j][h], bh[j][h + 1]);
                    MMA16816(acc[mi][ni], ah[mi], bl[j][h], bl[j][h + 1]);
                }
        }

        // epilogue: by 0 -> K fp32; by 1 -> q fp16; by 2 -> v fp16; by 3 -> S+bias fp32
#pragma unroll
        for (int mi = 0; mi < 2; mi++)
#pragma unroll
            for (int half = 0; half < 2; half++)
#pragma unroll
                for (int ni = 0; ni < 8; ni++) {
                    int r = row0 + m_base + mi * 16 + half * 8 + r_in;
                    int c = n_base + ni * 8 + c_in;
                    float2 v = make_float2(acc[mi][ni][half * 2], acc[mi][ni][half * 2 + 1]);
                    if (by == 0) {
                        *(float2*)(g_K + (size_t)r * 128 + c) = v;
                    } else if (by == 1) {
                        *(__half2*)(g_QVh + (size_t)r * 256 + c) = __floats2half2_rn(v.x, v.y);
                    } else if (by == 2) {
                        *(__half2*)(g_QVh + (size_t)r * 256 + 128 + c) = __floats2half2_rn(v.x, v.y);
                    } else {
                        v.x += __ldg(&bias[c]);
                        v.y += __ldg(&bias[c + 1]);
                        *(float2*)(g_S + (size_t)r * 128 + c) = v;
                    }
                }
        __syncthreads();   // prefetched buffer complete + current buffer free
    }
}

// ---------------- gated edge accumulation (shared by both agg kernels) ----------------
__device__ __forceinline__ void edge_accum(float4& acc, const float4& k, int s, int lane) {
    const __half* qvrow = g_QVh + (size_t)s * 256;
    uint2 qa = __ldg((const uint2*)qvrow + lane);        // q[lane*4 .. +4)
    uint2 va = __ldg((const uint2*)qvrow + 32 + lane);   // v[lane*4 .. +4)
    float2 q01 = h2f(qa.x), q23 = h2f(qa.y);
    float2 v01 = h2f(va.x), v23 = h2f(va.y);
    acc.x = fmaf(fsig(k.x + q01.x), v01.x, acc.x);
    acc.y = fmaf(fsig(k.y + q01.y), v01.y, acc.y);
    acc.z = fmaf(fsig(k.z + q23.x), v23.x, acc.z);
    acc.w = fmaf(fsig(k.w + q23.y), v23.y, acc.w);
}

// ---------------- layer-1 gated aggregation: warp per node, bf16 split output ----------------
__global__ void __launch_bounds__(256) agg128_l1(int n) {
    int node = blockIdx.x * 8 + (threadIdx.x >> 5);
    if (node >= n) return;
    int lane = threadIdx.x & 31;
    int beg = g_rowoff[node], end = g_rowoff[node + 1];
    const float4* kp = (const float4*)(g_K + (size_t)node * DD);
    float4 k = kp[lane];
    float4 acc = make_float4(0.f, 0.f, 0.f, 0.f);
#pragma unroll 2
    for (int e = beg; e < end; e++)
        edge_accum(acc, k, g_srcsorted[e], lane);
    const float4* sp = (const float4*)(g_S + (size_t)node * DD);
    float4 sv = sp[lane];
    float4 r = make_float4(fmaxf(acc.x + sv.x, 0.f), fmaxf(acc.y + sv.y, 0.f),
                           fmaxf(acc.z + sv.z, 0.f), fmaxf(acc.w + sv.w, 0.f));
    uint32_t h0, h1, l0, l1;
    pack_hl(r.x, r.y, h0, l0);
    pack_hl(r.z, r.w, h1, l1);
    size_t off = (size_t)node * DD + lane * 4;
    *(uint2*)(g_Ahi + off) = make_uint2(h0, h1);
    *(uint2*)(g_Alo + off) = make_uint2(l0, l1);
}

// ---------------- layer-2 aggregation FUSED with layer-3 projection ----------------
__global__ void __launch_bounds__(256) agg_proj3(
    const float* __restrict__ Wk, const float* __restrict__ Wq,
    const float* __restrict__ Wv, const float* __restrict__ Ws,
    const float* __restrict__ b, int n)
{
    __shared__ float w[4][128];
    int tid = threadIdx.x;
    if (tid < 128) { w[0][tid] = Wk[tid]; w[1][tid] = Wq[tid]; }
    else { int t = tid - 128; w[2][t] = Wv[t]; w[3][t] = Ws[t]; }
    __syncthreads();

    int node = blockIdx.x * 8 + (tid >> 5);
    if (node >= n) return;
    int lane = tid & 31;
    int beg = g_rowoff[node], end = g_rowoff[node + 1];
    const float4* kp = (const float4*)(g_K + (size_t)node * DD);
    float4 k = kp[lane];
    float4 acc = make_float4(0.f, 0.f, 0.f, 0.f);
#pragma unroll 2
    for (int e = beg; e < end; e++)
        edge_accum(acc, k, g_srcsorted[e], lane);
    const float4* sp = (const float4*)(g_S + (size_t)node * DD);
    float4 sv = sp[lane];
    float4 r = make_float4(fmaxf(acc.x + sv.x, 0.f), fmaxf(acc.y + sv.y, 0.f),
                           fmaxf(acc.z + sv.z, 0.f), fmaxf(acc.w + sv.w, 0.f));

    // four 128-dot-products (4 elems per lane + warp reduction)
    int c = lane * 4;
    float pk = r.x * w[0][c] + r.y * w[0][c + 1] + r.z * w[0][c + 2] + r.w * w[0][c + 3];
    float pq = r.x * w[1][c] + r.y * w[1][c + 1] + r.z * w[1][c + 2] + r.w * w[1][c + 3];
    float pv = r.x * w[2][c] + r.y * w[2][c + 1] + r.z * w[2][c + 2] + r.w * w[2][c + 3];
    float ps = r.x * w[3][c] + r.y * w[3][c + 1] + r.z * w[3][c + 2] + r.w * w[3][c + 3];
#pragma unroll
    for (int o = 16; o; o >>= 1) {
        pk += __shfl_xor_sync(0xFFFFFFFFu, pk, o);
        pq += __shfl_xor_sync(0xFFFFFFFFu, pq, o);
        pv += __shfl_xor_sync(0xFFFFFFFFu, pv, o);
        ps += __shfl_xor_sync(0xFFFFFFFFu, ps, o);
    }
    if (lane == 0) g_P3[node] = make_float4(pk, pq, pv, ps + b[0]);
}

// ---------------- layer 3 aggregation: thread per node ----------------
__global__ void agg3_k(float* __restrict__ out, int n) {
    int i = blockIdx.x * blockDim.x + threadIdx.x;
    if (i >= n) return;
    float4 p = g_P3[i];
    float acc = p.w;
    int beg = g_rowoff[i], end = g_rowoff[i + 1];
    for (int e = beg; e < end; e++) {
        float4 ps = __ldg(&g_P3[g_srcsorted[e]]);
        acc = fmaf(fsig(p.x + ps.y), ps.z, acc);
    }
    out[i] = acc;
}

// ---------------- launch ----------------
extern "C" void kernel_launch(void* const* d_in, const int* in_sizes, int n_in,
                              void* d_out, int out_size) {
    const float* x  = (const float*)d_in[0];
    const int*   ei = (const int*)d_in[1];
    const float* Wk1 = (const float*)d_in[2];
    const float* Wq1 = (const float*)d_in[3];
    const float* Wv1 = (const float*)d_in[4];
    const float* Ws1 = (const float*)d_in[5];
    const float* b1  = (const float*)d_in[6];
    const float* Wk2 = (const float*)d_in[7];
    const float* Wq2 = (const float*)d_in[8];
    const float* Wv2 = (const float*)d_in[9];
    const float* Ws2 = (const float*)d_in[10];
    const float* b2  = (const float*)d_in[11];
    const float* Wk3 = (const float*)d_in[12];
    const float* Wq3 = (const float*)d_in[13];
    const float* Wv3 = (const float*)d_in[14];
    const float* Ws3 = (const float*)d_in[15];
    const float* b3  = (const float*)d_in[16];

    int N = in_sizes[0] / DD;     // 100000
    int E = in_sizes[1] / 2;      // 1600000
    const int* src = ei;
    const int* dst = ei + E;

    const int SMEMSZ = 6 * TILE * 2;   // 208896 bytes
    cudaFuncSetAttribute(mma_gemm<0>, cudaFuncAttributeMaxDynamicSharedMemorySize, SMEMSZ);
    cudaFuncSetAttribute(mma_gemm<1>, cudaFuncAttributeMaxDynamicSharedMemorySize, SMEMSZ);

    int ab = (N + 7) / 8;

    // fork: CSR build on side stream, concurrent with layer-1 GEMM pipeline
    cudaStream_t s1;
    cudaStreamCreateWithFlags(&s1, cudaStreamNonBlocking);
    cudaEvent_t ev0, evCSR;
    cudaEventCreateWithFlags(&ev0, cudaEventDisableTiming);
    cudaEventCreateWithFlags(&evCSR, cudaEventDisableTiming);

    cudaEventRecord(ev0, 0);
    cudaStreamWaitEvent(s1, ev0, 0);
    zero_counts_k<<<(N + 255) / 256, 256, 0, s1>>>(N);
    hist_k<<<(E + 255) / 256, 256, 0, s1>>>(dst, E);
    scan_k<<<1, 1024, 0, s1>>>(N);
    scatter_k<<<(E + 255) / 256, 256, 0, s1>>>(src, dst, E);
    cudaEventRecord(evCSR, s1);

    // layer 1 (main stream; fp32 x consumed directly by GEMM)
    packw_k<<<256, 256>>>(Wk1, Wq1, Wv1, Ws1);
    mma_gemm<1><<<NBLK, 256, SMEMSZ>>>(b1, x, N);

    // join CSR before first aggregation
    cudaStreamWaitEvent(0, evCSR, 0);
    agg128_l1<<<ab, 256>>>(N);                   // ReLU + bf16 split write (feeds GEMM2)

    // layer 2
    packw_k<<<256, 256>>>(Wk2, Wq2, Wv2, Ws2);
    mma_gemm<0><<<NBLK, 256, SMEMSZ>>>(b2, nullptr, N);
    agg_proj3<<<ab, 256>>>(Wk3, Wq3, Wv3, Ws3, b3, N);   // agg2 + proj3 fused

    // layer 3
    agg3_k<<<(N + 255) / 256, 256>>>((float*)d_out, N);
}

// round 13
// speedup vs baseline: 1.0359x; 1.0359x over previous
#include <cuda_runtime.h>
#include <cuda_bf16.h>
#include <cuda_fp16.h>
#include <cstdint>
#include <cstring>

#define NN 100000
#define DD 128
#define EMAX 1600000
#define NP 100096          // 782 * 128 (padded rows)
#define NBLK 782
#define TSTRIDE 136        // padded bf16 row stride: conflict-free ldmatrix
#define TILE (128 * TSTRIDE)

// ---------------- scratch (device globals: no allocation allowed) ----------------
__device__ float g_K[NP * DD];
__device__ __half g_QVh[NP * 256];         // per node: q fp16[0..128), v fp16[128..256)
__device__ float g_S[NP * DD];
__device__ __nv_bfloat16 g_Ahi[NP * DD];   // layer-2 GEMM input (pad rows stay 0)
__device__ __nv_bfloat16 g_Alo[NP * DD];
__device__ __nv_bfloat16 g_Whi[512 * 128]; // [n_out][k], n_out = concat(k,q,v,s)
__device__ __nv_bfloat16 g_Wlo[512 * 128];
__device__ float4 g_P3[NP];
__device__ int g_counts[NN];
__device__ int g_rowoff[NN + 1];
__device__ int g_cursor[NN];
__device__ int g_srcsorted[EMAX];

// ---------------- helpers ----------------
__device__ __forceinline__ uint32_t smem_u32(const void* p) {
    uint32_t a;
    asm("{ .reg .u64 t; cvta.to.shared.u64 t, %1; cvt.u32.u64 %0, t; }" : "=r"(a) : "l"(p));
    return a;
}

#define LDSM_X4(r0, r1, r2, r3, addr)                                          \
    asm volatile("ldmatrix.sync.aligned.m8n8.x4.shared.b16 {%0,%1,%2,%3}, [%4];" \
                 : "=r"(r0), "=r"(r1), "=r"(r2), "=r"(r3) : "r"(addr))

#define MMA16816(d, a, b0, b1)                                                 \
    asm volatile("mma.sync.aligned.m16n8k16.row.col.f32.bf16.bf16.f32 "        \
                 "{%0,%1,%2,%3}, {%4,%5,%6,%7}, {%8,%9}, {%0,%1,%2,%3};"       \
                 : "+f"((d)[0]), "+f"((d)[1]), "+f"((d)[2]), "+f"((d)[3])      \
                 : "r"((a)[0]), "r"((a)[1]), "r"((a)[2]), "r"((a)[3]),         \
                   "r"(b0), "r"(b1))

// ---------------- sigmoid via HW tanh: 1 MUFU instead of 2 ----------------
// sigmoid(t) = 0.5 * tanh(t/2) + 0.5 ; tanh.approx.f32 max err ~1.4e-5
__device__ __forceinline__ float fsig(float t) {
    float th;
    asm("tanh.approx.f32 %0, %1;" : "=f"(th) : "f"(t * 0.5f));
    return fmaf(th, 0.5f, 0.5f);
}

// fp16 pair (as uint32) -> float2
__device__ __forceinline__ float2 h2f(uint32_t u) {
    __half2 h;
    memcpy(&h, &u, 4);
    return __half22float2(h);
}

// safe bf16 hi/lo split pack: two floats -> (hi_pair, lo_pair) uint32s
__device__ __forceinline__ void pack_hl(float a, float b, uint32_t& hp, uint32_t& lp) {
    __nv_bfloat16 ha = __float2bfloat16(a);
    __nv_bfloat16 hb = __float2bfloat16(b);
    __nv_bfloat16 la = __float2bfloat16(a - __bfloat162float(ha));
    __nv_bfloat16 lb = __float2bfloat16(b - __bfloat162float(hb));
    hp = (uint32_t)__bfloat16_as_ushort(ha) | ((uint32_t)__bfloat16_as_ushort(hb) << 16);
    lp = (uint32_t)__bfloat16_as_ushort(la) | ((uint32_t)__bfloat16_as_ushort(lb) << 16);
}

// ---------------- CSR build ----------------
__global__ void zero_counts_k(int n) {
    int i = blockIdx.x * blockDim.x + threadIdx.x;
    if (i < n) g_counts[i] = 0;
}
__global__ void hist_k(const int* __restrict__ dst, int e) {
    int i = blockIdx.x * blockDim.x + threadIdx.x;
    if (i < e) atomicAdd(&g_counts[dst[i]], 1);
}
__global__ void scan_k(int n) {
    __shared__ int sums[1024];
    int tid = threadIdx.x;
    int chunk = (n + 1023) >> 10;
    int b = tid * chunk, e = min(b + chunk, n);
    int s = 0;
    for (int i = b; i < e; i++) s += g_counts[i];
    sums[tid] = s;
    __syncthreads();
    for (int off = 1; off < 1024; off <<= 1) {
        int v = (tid >= off) ? sums[tid - off] : 0;
        __syncthreads();
        sums[tid] += v;
        __syncthreads();
    }
    int run = tid ? sums[tid - 1] : 0;
    for (int i = b; i < e; i++) {
        g_rowoff[i] = run;
        g_cursor[i] = run;
        run += g_counts[i];
    }
    if (tid == 1023) g_rowoff[n] = sums[1023];
}
__global__ void scatter_k(const int* __restrict__ src, const int* __restrict__ dst, int e) {
    int i = blockIdx.x * blockDim.x + threadIdx.x;
    if (i < e) {
        int p = atomicAdd(&g_cursor[dst[i]], 1);
        g_srcsorted[p] = src[i];
    }
}

// ---------------- weight packing ----------------
__global__ void packw_k(const float* __restrict__ Wk, const float* __restrict__ Wq,
                        const float* __restrict__ Wv, const float* __restrict__ Ws) {
    int i = blockIdx.x * blockDim.x + threadIdx.x;   // 512*128
    if (i >= 512 * 128) return;
    int n = i >> 7, k = i & 127;
    const float* W = (n < 128) ? Wk : (n < 256) ? Wq : (n < 384) ? Wv : Ws;
    float v = W[k * 128 + (n & 127)];
    __nv_bfloat16 h = __float2bfloat16(v);
    g_Whi[i] = h;
    g_Wlo[i] = __float2bfloat16(v - __bfloat162float(h));
}

// ---------------- mma.sync bf16 split GEMM, A-resident column loop ----------------
// CTA: 128 rows x ALL 512 cols; A (hi+lo) loaded once, 4 col-blocks with
// double-buffered B tiles. K/S epilogue fp32; Q/V epilogue fp16 (halves agg traffic).
// acc = Ahi*Bhi + Alo*Bhi + Ahi*Blo  (fp32 accum; rel err ~2^-17)
__device__ __forceinline__ void load_B(__nv_bfloat16* Bh, __nv_bfloat16* Bl, int by, int tid) {
    const __nv_bfloat16* GBH = g_Whi + (size_t)by * 128 * 128;
    const __nv_bfloat16* GBL = g_Wlo + (size_t)by * 128 * 128;
#pragma unroll
    for (int i = 0; i < 8; i++) {
        int c = tid + i * 256;
        int r = c >> 4, col = (c & 15) * 8;
        *(uint4*)(Bh + r * TSTRIDE + col) = *(const uint4*)(GBH + r * 128 + col);
        *(uint4*)(Bl + r * TSTRIDE + col) = *(const uint4*)(GBL + r * 128 + col);
    }
}

template <int SRC>
__global__ void __launch_bounds__(256, 1) mma_gemm(
    const float* __restrict__ bias, const float* __restrict__ xin, int nrows)
{
    extern __shared__ __nv_bfloat16 sm[];
    __nv_bfloat16* Ah = sm;
    __nv_bfloat16* Al = sm + TILE;
    __nv_bfloat16* Bbuf[2][2] = {{sm + 2 * TILE, sm + 3 * TILE},
                                 {sm + 4 * TILE, sm + 5 * TILE}};

    int tid = threadIdx.x;
    int row0 = blockIdx.x * 128;

    // ---- load A once ----
    if (SRC == 0) {
#pragma unroll
        for (int i = 0; i < 8; i++) {
            int c = tid + i * 256;
            int r = c >> 4, col = (c & 15) * 8;
            *(uint4*)(Ah + r * TSTRIDE + col) = *(const uint4*)(g_Ahi + (size_t)(row0 + r) * 128 + col);
            *(uint4*)(Al + r * TSTRIDE + col) = *(const uint4*)(g_Alo + (size_t)(row0 + r) * 128 + col);
        }
    } else {
#pragma unroll
        for (int i = 0; i < 16; i++) {
            int c = tid + i * 256;
            int r = c >> 5, col = (c & 31) * 4;
            float4 v = make_float4(0.f, 0.f, 0.f, 0.f);
            if (row0 + r < nrows)
                v = *(const float4*)(xin + (size_t)(row0 + r) * 128 + col);
            uint32_t h0, l0, h1, l1;
            pack_hl(v.x, v.y, h0, l0);
            pack_hl(v.z, v.w, h1, l1);
            *(uint2*)(Ah + r * TSTRIDE + col) = make_uint2(h0, h1);
            *(uint2*)(Al + r * TSTRIDE + col) = make_uint2(l0, l1);
        }
    }
    // ---- B for col-block 0 ----
    load_B(Bbuf[0][0], Bbuf[0][1], 0, tid);
    __syncthreads();

    int w = tid >> 5, lane = tid & 31;
    int m_base = (w & 3) * 32;
    int n_base = (w >> 2) * 64;

    // ldmatrix address patterns
    int a_row = lane & 15, a_colsel = (lane >> 4) * 8;          // A x4: m16 x k16
    int b_grp = lane >> 3;                                      // B x4: n16 x k16
    int b_row = (b_grp >> 1) * 8 + (lane & 7);
    int b_col = (b_grp & 1) * 8;

    uint32_t sAh = smem_u32(Ah), sAl = smem_u32(Al);
    int r_in = lane >> 2;
    int c_in = (lane & 3) * 2;

    for (int by = 0; by < 4; by++) {
        int buf = by & 1;
        // prefetch next col-block's B into the other buffer (hidden under MMAs)
        if (by < 3) load_B(Bbuf[buf ^ 1][0], Bbuf[buf ^ 1][1], by + 1, tid);

        uint32_t sBh = smem_u32(Bbuf[buf][0]), sBl = smem_u32(Bbuf[buf][1]);

        float acc[2][8][4];
#pragma unroll
        for (int mi = 0; mi < 2; mi++)
#pragma unroll
            for (int ni = 0; ni < 8; ni++)
#pragma unroll
                for (int j = 0; j < 4; j++) acc[mi][ni][j] = 0.0f;

#pragma unroll
        for (int ks = 0; ks < 8; ks++) {
            int k0 = ks * 16;
            uint32_t ah[2][4], al[2][4], bh[4][4], bl[4][4];
#pragma unroll
            for (int mi = 0; mi < 2; mi++) {
                uint32_t off = (uint32_t)((m_base + mi * 16 + a_row) * TSTRIDE + k0 + a_colsel) * 2;
                LDSM_X4(ah[mi][0], ah[mi][1], ah[mi][2], ah[mi][3], sAh + off);
                LDSM_X4(al[mi][0], al[mi][1], al[mi][2], al[mi][3], sAl + off);
            }
#pragma unroll
            for (int j = 0; j < 4; j++) {
                uint32_t off = (uint32_t)((n_base + j * 16 + b_row) * TSTRIDE + k0 + b_col) * 2;
                LDSM_X4(bh[j][0], bh[j][1], bh[j][2], bh[j][3], sBh + off);
                LDSM_X4(bl[j][0], bl[j][1], bl[j][2], bl[j][3], sBl + off);
            }
#pragma unroll
            for (int mi = 0; mi < 2; mi++)
#pragma unroll
                for (int ni = 0; ni < 8; ni++) {
                    int j = ni >> 1, h = (ni & 1) * 2;
                    MMA16816(acc[mi][ni], ah[mi], bh[j][h], bh[j][h + 1]);
                    MMA16816(acc[mi][ni], al[mi], bh[j][h], bh[j][h + 1]);
                    MMA16816(acc[mi][ni], ah[mi], bl[j][h], bl[j][h + 1]);
                }
        }

        // epilogue: by 0 -> K fp32; by 1 -> q fp16; by 2 -> v fp16; by 3 -> S+bias fp32
#pragma unroll
        for (int mi = 0; mi < 2; mi++)
#pragma unroll
            for (int half = 0; half < 2; half++)
#pragma unroll
                for (int ni = 0; ni < 8; ni++) {
                    int r = row0 + m_base + mi * 16 + half * 8 + r_in;
                    int c = n_base + ni * 8 + c_in;
                    float2 v = make_float2(acc[mi][ni][half * 2], acc[mi][ni][half * 2 + 1]);
                    if (by == 0) {
                        *(float2*)(g_K + (size_t)r * 128 + c) = v;
                    } else if (by == 1) {
                        *(__half2*)(g_QVh + (size_t)r * 256 + c) = __floats2half2_rn(v.x, v.y);
                    } else if (by == 2) {
                        *(__half2*)(g_QVh + (size_t)r * 256 + 128 + c) = __floats2half2_rn(v.x, v.y);
                    } else {
                        v.x += __ldg(&bias[c]);
                        v.y += __ldg(&bias[c + 1]);
                        *(float2*)(g_S + (size_t)r * 128 + c) = v;
                    }
                }
        __syncthreads();   // prefetched buffer complete + current buffer free
    }
}

// ---------------- gated edge accumulation (shared by both agg kernels) ----------------
__device__ __forceinline__ void edge_accum(float4& acc, const float4& k, int s, int lane) {
    const __half* qvrow = g_QVh + (size_t)s * 256;
    uint2 qa = __ldg((const uint2*)qvrow + lane);        // q[lane*4 .. +4)
    uint2 va = __ldg((const uint2*)qvrow + 32 + lane);   // v[lane*4 .. +4)
    float2 q01 = h2f(qa.x), q23 = h2f(qa.y);
    float2 v01 = h2f(va.x), v23 = h2f(va.y);
    acc.x = fmaf(fsig(k.x + q01.x), v01.x, acc.x);
    acc.y = fmaf(fsig(k.y + q01.y), v01.y, acc.y);
    acc.z = fmaf(fsig(k.z + q23.x), v23.x, acc.z);
    acc.w = fmaf(fsig(k.w + q23.y), v23.y, acc.w);
}

// ---------------- layer-1 gated aggregation: warp per node, bf16 split output ----------------
__global__ void __launch_bounds__(256) agg128_l1(int n) {
    int node = blockIdx.x * 8 + (threadIdx.x >> 5);
    if (node >= n) return;
    int lane = threadIdx.x & 31;
    int beg = g_rowoff[node], end = g_rowoff[node + 1];
    const float4* kp = (const float4*)(g_K + (size_t)node * DD);
    float4 k = kp[lane];
    float4 acc = make_float4(0.f, 0.f, 0.f, 0.f);
#pragma unroll 2
    for (int e = beg; e < end; e++)
        edge_accum(acc, k, g_srcsorted[e], lane);
    const float4* sp = (const float4*)(g_S + (size_t)node * DD);
    float4 sv = sp[lane];
    float4 r = make_float4(fmaxf(acc.x + sv.x, 0.f), fmaxf(acc.y + sv.y, 0.f),
                           fmaxf(acc.z + sv.z, 0.f), fmaxf(acc.w + sv.w, 0.f));
    uint32_t h0, h1, l0, l1;
    pack_hl(r.x, r.y, h0, l0);
    pack_hl(r.z, r.w, h1, l1);
    size_t off = (size_t)node * DD + lane * 4;
    *(uint2*)(g_Ahi + off) = make_uint2(h0, h1);
    *(uint2*)(g_Alo + off) = make_uint2(l0, l1);
}

// ---------------- layer-2 aggregation FUSED with layer-3 projection ----------------
__global__ void __launch_bounds__(256) agg_proj3(
    const float* __restrict__ Wk, const float* __restrict__ Wq,
    const float* __restrict__ Wv, const float* __restrict__ Ws,
    const float* __restrict__ b, int n)
{
    __shared__ float w[4][128];
    int tid = threadIdx.x;
    if (tid < 128) { w[0][tid] = Wk[tid]; w[1][tid] = Wq[tid]; }
    else { int t = tid - 128; w[2][t] = Wv[t]; w[3][t] = Ws[t]; }
    __syncthreads();

    int node = blockIdx.x * 8 + (tid >> 5);
    if (node >= n) return;
    int lane = tid & 31;
    int beg = g_rowoff[node], end = g_rowoff[node + 1];
    const float4* kp = (const float4*)(g_K + (size_t)node * DD);
    float4 k = kp[lane];
    float4 acc = make_float4(0.f, 0.f, 0.f, 0.f);
#pragma unroll 2
    for (int e = beg; e < end; e++)
        edge_accum(acc, k, g_srcsorted[e], lane);
    const float4* sp = (const float4*)(g_S + (size_t)node * DD);
    float4 sv = sp[lane];
    float4 r = make_float4(fmaxf(acc.x + sv.x, 0.f), fmaxf(acc.y + sv.y, 0.f),
                           fmaxf(acc.z + sv.z, 0.f), fmaxf(acc.w + sv.w, 0.f));

    // four 128-dot-products (4 elems per lane + warp reduction)
    int c = lane * 4;
    float pk = r.x * w[0][c] + r.y * w[0][c + 1] + r.z * w[0][c + 2] + r.w * w[0][c + 3];
    float pq = r.x * w[1][c] + r.y * w[1][c + 1] + r.z * w[1][c + 2] + r.w * w[1][c + 3];
    float pv = r.x * w[2][c] + r.y * w[2][c + 1] + r.z * w[2][c + 2] + r.w * w[2][c + 3];
    float ps = r.x * w[3][c] + r.y * w[3][c + 1] + r.z * w[3][c + 2] + r.w * w[3][c + 3];
#pragma unroll
    for (int o = 16; o; o >>= 1) {
        pk += __shfl_xor_sync(0xFFFFFFFFu, pk, o);
        pq += __shfl_xor_sync(0xFFFFFFFFu, pq, o);
        pv += __shfl_xor_sync(0xFFFFFFFFu, pv, o);
        ps += __shfl_xor_sync(0xFFFFFFFFu, ps, o);
    }
    if (lane == 0) g_P3[node] = make_float4(pk, pq, pv, ps + b[0]);
}

// ---------------- layer 3 aggregation: thread per node ----------------
__global__ void agg3_k(float* __restrict__ out, int n) {
    int i = blockIdx.x * blockDim.x + threadIdx.x;
    if (i >= n) return;
    float4 p = g_P3[i];
    float acc = p.w;
    int beg = g_rowoff[i], end = g_rowoff[i + 1];
    for (int e = beg; e < end; e++) {
        float4 ps = __ldg(&g_P3[g_srcsorted[e]]);
        acc = fmaf(fsig(p.x + ps.y), ps.z, acc);
    }
    out[i] = acc;
}

// ---------------- launch ----------------
extern "C" void kernel_launch(void* const* d_in, const int* in_sizes, int n_in,
                              void* d_out, int out_size) {
    const float* x  = (const float*)d_in[0];
    const int*   ei = (const int*)d_in[1];
    const float* Wk1 = (const float*)d_in[2];
    const float* Wq1 = (const float*)d_in[3];
    const float* Wv1 = (const float*)d_in[4];
    const float* Ws1 = (const float*)d_in[5];
    const float* b1  = (const float*)d_in[6];
    const float* Wk2 = (const float*)d_in[7];
    const float* Wq2 = (const float*)d_in[8];
    const float* Wv2 = (const float*)d_in[9];
    const float* Ws2 = (const float*)d_in[10];
    const float* b2  = (const float*)d_in[11];
    const float* Wk3 = (const float*)d_in[12];
    const float* Wq3 = (const float*)d_in[13];
    const float* Wv3 = (const float*)d_in[14];
    const float* Ws3 = (const float*)d_in[15];
    const float* b3  = (const float*)d_in[16];

    int N = in_sizes[0] / DD;     // 100000
    int E = in_sizes[1] / 2;      // 1600000
    const int* src = ei;
    const int* dst = ei + E;

    const int SMEMSZ = 6 * TILE * 2;   // 208896 bytes
    cudaFuncSetAttribute(mma_gemm<0>, cudaFuncAttributeMaxDynamicSharedMemorySize, SMEMSZ);
    cudaFuncSetAttribute(mma_gemm<1>, cudaFuncAttributeMaxDynamicSharedMemorySize, SMEMSZ);

    int ab = (N + 7) / 8;

    // fork: CSR build on side stream, concurrent with layer-1 GEMM pipeline
    cudaStream_t s1;
    cudaStreamCreateWithFlags(&s1, cudaStreamNonBlocking);
    cudaEvent_t ev0, evCSR;
    cudaEventCreateWithFlags(&ev0, cudaEventDisableTiming);
    cudaEventCreateWithFlags(&evCSR, cudaEventDisableTiming);

    cudaEventRecord(ev0, 0);
    cudaStreamWaitEvent(s1, ev0, 0);
    zero_counts_k<<<(N + 255) / 256, 256, 0, s1>>>(N);
    hist_k<<<(E + 255) / 256, 256, 0, s1>>>(dst, E);
    scan_k<<<1, 1024, 0, s1>>>(N);
    scatter_k<<<(E + 255) / 256, 256, 0, s1>>>(src, dst, E);
    cudaEventRecord(evCSR, s1);

    // layer 1 (main stream; fp32 x consumed directly by GEMM)
    packw_k<<<256, 256>>>(Wk1, Wq1, Wv1, Ws1);
    mma_gemm<1><<<NBLK, 256, SMEMSZ>>>(b1, x, N);

    // join CSR before first aggregation
    cudaStreamWaitEvent(0, evCSR, 0);
    agg128_l1<<<ab, 256>>>(N);                   // ReLU + bf16 split write (feeds GEMM2)

    // layer 2
    packw_k<<<256, 256>>>(Wk2, Wq2, Wv2, Ws2);
    mma_gemm<0><<<NBLK, 256, SMEMSZ>>>(b2, nullptr, N);
    agg_proj3<<<ab, 256>>>(Wk3, Wq3, Wv3, Ws3, b3, N);   // agg2 + proj3 fused

    // layer 3
    agg3_k<<<(N + 255) / 256, 256>>>((float*)d_out, N);
}